// round 13
// baseline (speedup 1.0000x reference)
#include <cuda_runtime.h>
#include <cuda_fp16.h>

#define NN 100000
#define NE 3200000

// ---- scratch (static __device__, zero-init at module load) ----
__device__ int    g_deg[NN];         // degree counters (reset by k_nodeA each run)
__device__ float  g_dinv[NN];        // rsqrt(1+deg)
__device__ float2 g_s[NN];           // s[i] = dinv[i] * x[i]  (rank-2 coords)
__device__ float2 g_ab[NN];          // conv1 accumulator in rank-2 basis (init = s[i])
// r-side packed record, ONE 16B gather per edge:
//   .x = half2(pr.x, pr.y)  .y = half2(pr.z, pr.w)   (edge-MLP r-projection, fp16)
//   .z = bits(z.x)          .w = bits(z.y)           (conv2 operand, fp32)
__device__ uint4  g_r16[NN];
__device__ uint2  g_pc16[NN];        // c-side proj We[17:33]^T h, 4 x fp16 (8B gather)
__device__ float2 g_ox[NN];          // conv2 accumulator (unscaled)
__device__ int2   g_edge[NE];        // (row, col) packed

// ---- fp16 pack/unpack helpers ----
__device__ __forceinline__ unsigned pack_h2(float a, float b) {
    unsigned lo = __half_as_ushort(__float2half_rn(a));
    unsigned hi = __half_as_ushort(__float2half_rn(b));
    return lo | (hi << 16);
}
__device__ __forceinline__ float2 unpack_h2(unsigned u) {
    float a = __half2float(__ushort_as_half((unsigned short)(u & 0xFFFFu)));
    float b = __half2float(__ushort_as_half((unsigned short)(u >> 16)));
    return make_float2(a, b);
}

// ---- vectorized L2 reduction (global address space) ----
__device__ __forceinline__ void red_add_v2(float2* addr, float a, float b) {
    unsigned long long ga;
    asm("cvta.to.global.u64 %0, %1;" : "=l"(ga) : "l"(addr));
    asm volatile("red.global.add.v2.f32 [%0], {%1, %2};"
                 :: "l"(ga), "f"(a), "f"(b) : "memory");
}

// 1) decode edge index (2 edges/thread, streaming loads) -> packed int2 + degree count.
//    int64-vs-int32 layout detected per warp: odd words of the first 16 int64s all
//    zero <=> int64 (random indices in [0,100000) are never all-zero there).
__global__ void k_deg(const int* __restrict__ ei32) {
    int lane = threadIdx.x & 31;
    int w = ei32[lane];
    unsigned mask = __ballot_sync(0xFFFFFFFFu, (lane & 1) ? (w == 0) : true);
    bool is64 = (mask == 0xFFFFFFFFu);

    int t = blockIdx.x * blockDim.x + threadIdx.x;
    if (t >= NE / 2) return;
    int r0, c0, r1, c1;
    if (is64) {
        int4 rr = __ldcs((const int4*)ei32 + t);              // longs 2t,2t+1 (rows)
        int4 cc = __ldcs((const int4*)ei32 + (NE / 2) + t);   // longs NE+2t.. (cols)
        r0 = rr.x; r1 = rr.z;
        c0 = cc.x; c1 = cc.z;
    } else {
        int2 rr = __ldcs((const int2*)ei32 + t);
        int2 cc = __ldcs((const int2*)(ei32 + NE) + t);
        r0 = rr.x; r1 = rr.y;
        c0 = cc.x; c1 = cc.y;
    }
    ((int4*)g_edge)[t] = make_int4(r0, c0, r1, c1);
    atomicAdd(&g_deg[c0], 1);
    atomicAdd(&g_deg[c1], 1);
}

// 2) dinv = rsqrt(1+deg); reset deg for next replay; s = dinv*x; ab init = s
__global__ void k_nodeA(const float* __restrict__ x) {
    int i = blockIdx.x * blockDim.x + threadIdx.x;
    if (i >= NN) return;
    int cnt = g_deg[i];
    g_deg[i] = 0;                          // restore zero invariant for graph replay
    float d = rsqrtf((float)(1 + cnt));
    g_dinv[i] = d;
    float2 xv = ((const float2*)x)[i];
    float2 s = make_float2(xv.x * d, xv.y * d);
    g_s[i]  = s;
    g_ab[i] = s;
}

// 3) conv1 scatter in rank-2 basis (1 edge/thread): ab[col] += s[row]
__global__ void k_scat1() {
    int e = blockIdx.x * blockDim.x + threadIdx.x;
    if (e >= NE) return;
    int2 rc = g_edge[e];
    float2 s = g_s[rc.x];
    red_add_v2(&g_ab[rc.y], s.x, s.y);
}

// 4) expand: h = dinv*(ab.x*W1row0 + ab.y*W1row1) + b1;
//    pr = We[0:16]^T h (fp16), pc = We[17:33]^T h (fp16), z = (h@W2)*dinv; ox init = z
__global__ void k_nodeB(const float* __restrict__ W1, const float* __restrict__ b1,
                        const float* __restrict__ W2, const float* __restrict__ We) {
    int i = blockIdx.x * blockDim.x + threadIdx.x;
    if (i >= NN) return;
    float d = g_dinv[i];
    float2 ab = g_ab[i];
    float ax = ab.x * d, bx = ab.y * d;
    float z0 = 0.f, z1 = 0.f;
    float4 pr = make_float4(0.f, 0.f, 0.f, 0.f);
    float4 pc = make_float4(0.f, 0.f, 0.f, 0.f);
#pragma unroll
    for (int q = 0; q < 4; q++) {
        float4 w0 = ((const float4*)W1)[q];
        float4 w1 = ((const float4*)W1)[4 + q];
        float4 bq = ((const float4*)b1)[q];
        float4 h;
        h.x = fmaf(ax, w0.x, fmaf(bx, w1.x, bq.x));
        h.y = fmaf(ax, w0.y, fmaf(bx, w1.y, bq.y));
        h.z = fmaf(ax, w0.z, fmaf(bx, w1.z, bq.z));
        h.w = fmaf(ax, w0.w, fmaf(bx, w1.w, bq.w));
        float hv[4] = {h.x, h.y, h.z, h.w};
#pragma unroll
        for (int j = 0; j < 4; j++) {
            int k = q * 4 + j;
            float s = hv[j];
            float2 w2 = ((const float2*)W2)[k];
            z0 = fmaf(s, w2.x, z0);
            z1 = fmaf(s, w2.y, z1);
            float4 wr = ((const float4*)We)[k];
            float4 wc = ((const float4*)We)[17 + k];
            pr.x = fmaf(s, wr.x, pr.x); pr.y = fmaf(s, wr.y, pr.y);
            pr.z = fmaf(s, wr.z, pr.z); pr.w = fmaf(s, wr.w, pr.w);
            pc.x = fmaf(s, wc.x, pc.x); pc.y = fmaf(s, wc.y, pc.y);
            pc.z = fmaf(s, wc.z, pc.z); pc.w = fmaf(s, wc.w, pc.w);
        }
    }
    uint4 rrec;
    rrec.x = pack_h2(pr.x, pr.y);
    rrec.y = pack_h2(pr.z, pr.w);
    rrec.z = __float_as_uint(z0 * d);
    rrec.w = __float_as_uint(z1 * d);
    g_r16[i]  = rrec;
    g_pc16[i] = make_uint2(pack_h2(pc.x, pc.y), pack_h2(pc.z, pc.w));
    g_ox[i]   = make_float2(z0 * d, z1 * d);
}

// 5) edge pass (1 edge/thread): acc = pr[r]+pc[c]+ea*We16+be -> relu -> log_softmax(4)
//    r-side = ONE 16B gather; c-side = ONE 8B gather + red; streaming single-use streams
__global__ void k_edge(const float* __restrict__ ea,
                       const float* __restrict__ We,
                       const float* __restrict__ be,
                       float* __restrict__ out_e) {
    int e = blockIdx.x * blockDim.x + threadIdx.x;
    if (e >= NE) return;
    float4 w16 = __ldg((const float4*)We + 16);
    float4 bev = __ldg((const float4*)be);

    int2 rc = g_edge[e];
    int r = rc.x, c = rc.y;

    uint4  rr = g_r16[r];                       // single 16B r-side gather
    float2 p01 = unpack_h2(rr.x);
    float2 p23 = unpack_h2(rr.y);
    float  zx = __uint_as_float(rr.z);
    float  zy = __uint_as_float(rr.w);
    uint2  cc = g_pc16[c];                      // single 8B c-side gather
    float2 q01 = unpack_h2(cc.x);
    float2 q23 = unpack_h2(cc.y);
    float  eav = __ldcs(ea + e);

    float4 acc;
    acc.x = fmaf(eav, w16.x, bev.x) + p01.x + q01.x;
    acc.y = fmaf(eav, w16.y, bev.y) + p01.y + q01.y;
    acc.z = fmaf(eav, w16.z, bev.z) + p23.x + q23.x;
    acc.w = fmaf(eav, w16.w, bev.w) + p23.y + q23.y;

    acc.x = fmaxf(acc.x, 0.f); acc.y = fmaxf(acc.y, 0.f);
    acc.z = fmaxf(acc.z, 0.f); acc.w = fmaxf(acc.w, 0.f);
    float m = fmaxf(fmaxf(acc.x, acc.y), fmaxf(acc.z, acc.w));
    float s = __expf(acc.x - m) + __expf(acc.y - m) +
              __expf(acc.z - m) + __expf(acc.w - m);
    float l = m + __logf(s);
    __stcs((float4*)out_e + e,
           make_float4(acc.x - l, acc.y - l, acc.z - l, acc.w - l));

    red_add_v2(&g_ox[c], zx, zy);
}

// 6) node output: log_softmax(ox_acc*dinv + b2) over 2 classes
__global__ void k_nodeC(const float* __restrict__ b2, float* __restrict__ out_n) {
    int i = blockIdx.x * blockDim.x + threadIdx.x;
    if (i >= NN) return;
    float d = g_dinv[i];
    float2 bb = *((const float2*)b2);
    float2 v = g_ox[i];
    v.x = fmaf(v.x, d, bb.x);
    v.y = fmaf(v.y, d, bb.y);
    float m = fmaxf(v.x, v.y);
    float l = m + __logf(__expf(v.x - m) + __expf(v.y - m));
    ((float2*)out_n)[i] = make_float2(v.x - l, v.y - l);
}

extern "C" void kernel_launch(void* const* d_in, const int* in_sizes, int n_in,
                              void* d_out, int out_size) {
    const float *x = 0, *ea = 0, *W1 = 0, *b1 = 0, *We = 0, *be = 0, *W2 = 0, *b2 = 0;
    const int* ei32 = 0;
    for (int i = 0; i < n_in; i++) {
        switch (in_sizes[i]) {
            case 200000:   x    = (const float*)d_in[i]; break;
            case 6400000:  ei32 = (const int*)d_in[i];   break;
            case 12800000: ei32 = (const int*)d_in[i];   break;
            case 3200000:  ea   = (const float*)d_in[i]; break;
            case 132:      We   = (const float*)d_in[i]; break;
            case 16:       b1   = (const float*)d_in[i]; break;
            case 4:        be   = (const float*)d_in[i]; break;
            case 2:        b2   = (const float*)d_in[i]; break;
            case 32:
                if (!W1) W1 = (const float*)d_in[i];
                else     W2 = (const float*)d_in[i];
                break;
            default: break;
        }
    }

    float* out = (float*)d_out;
    float* out_n = out;             // [N,2]
    float* out_e = out + 2 * NN;    // [E,4]

    const int BT_N = 256;
    const int BT_E = 256;
    const int NB_N  = (NN + BT_N - 1) / BT_N;
    const int NB_E  = (NE + BT_E - 1) / BT_E;
    const int NB_E2 = (NE / 2 + 512 - 1) / 512;

    k_deg   <<<NB_E2, 512>>>(ei32);
    k_nodeA <<<NB_N, BT_N>>>(x);
    k_scat1 <<<NB_E, BT_E>>>();
    k_nodeB <<<NB_N, BT_N>>>(W1, b1, W2, We);
    k_edge  <<<NB_E, BT_E>>>(ea, We, be, out_e);
    k_nodeC <<<NB_N, BT_N>>>(b2, out_n);
}

// round 14
// speedup vs baseline: 1.0012x; 1.0012x over previous
#include <cuda_runtime.h>
#include <cuda_fp16.h>

#define NN 100000
#define NE 3200000

// ---- scratch (static __device__, zero-init at module load) ----
__device__ int    g_deg[NN];         // degree counters (reset by k_nodeA each run)
__device__ float  g_dinv[NN];        // rsqrt(1+deg)
__device__ float2 g_s[NN];           // s[i] = dinv[i] * x[i]  (rank-2 coords)
__device__ float2 g_ab[NN];          // conv1 accumulator in rank-2 basis (init = s[i])
// r-side packed record, ONE 16B gather per edge:
//   .x = half2(pr.x, pr.y)  .y = half2(pr.z, pr.w)   (edge-MLP r-projection, fp16)
//   .z = bits(z.x)          .w = bits(z.y)           (conv2 operand, fp32)
__device__ uint4  g_r16[NN];
__device__ float4 g_pc[NN];          // c-side proj: We[17:33]^T h  (fp32)
__device__ float2 g_ox[NN];          // conv2 accumulator (unscaled)
__device__ int2   g_edge[NE];        // (row, col) packed

// ---- fp16 pack/unpack helpers ----
__device__ __forceinline__ unsigned pack_h2(float a, float b) {
    unsigned lo = __half_as_ushort(__float2half_rn(a));
    unsigned hi = __half_as_ushort(__float2half_rn(b));
    return lo | (hi << 16);
}
__device__ __forceinline__ float2 unpack_h2(unsigned u) {
    float a = __half2float(__ushort_as_half((unsigned short)(u & 0xFFFFu)));
    float b = __half2float(__ushort_as_half((unsigned short)(u >> 16)));
    return make_float2(a, b);
}

// ---- vectorized L2 reduction (global address space) ----
__device__ __forceinline__ void red_add_v2(float2* addr, float a, float b) {
    unsigned long long ga;
    asm("cvta.to.global.u64 %0, %1;" : "=l"(ga) : "l"(addr));
    asm volatile("red.global.add.v2.f32 [%0], {%1, %2};"
                 :: "l"(ga), "f"(a), "f"(b) : "memory");
}

// 1) decode edge index (2 edges/thread, streaming loads) -> packed int2 + degree count.
//    int64-vs-int32 layout detected per warp: odd words of the first 16 int64s all
//    zero <=> int64 (random indices in [0,100000) are never all-zero there).
__global__ void k_deg(const int* __restrict__ ei32) {
    int lane = threadIdx.x & 31;
    int w = ei32[lane];
    unsigned mask = __ballot_sync(0xFFFFFFFFu, (lane & 1) ? (w == 0) : true);
    bool is64 = (mask == 0xFFFFFFFFu);

    int t = blockIdx.x * blockDim.x + threadIdx.x;
    if (t >= NE / 2) return;
    int r0, c0, r1, c1;
    if (is64) {
        int4 rr = __ldcs((const int4*)ei32 + t);              // longs 2t,2t+1 (rows)
        int4 cc = __ldcs((const int4*)ei32 + (NE / 2) + t);   // longs NE+2t.. (cols)
        r0 = rr.x; r1 = rr.z;
        c0 = cc.x; c1 = cc.z;
    } else {
        int2 rr = __ldcs((const int2*)ei32 + t);
        int2 cc = __ldcs((const int2*)(ei32 + NE) + t);
        r0 = rr.x; r1 = rr.y;
        c0 = cc.x; c1 = cc.y;
    }
    ((int4*)g_edge)[t] = make_int4(r0, c0, r1, c1);
    atomicAdd(&g_deg[c0], 1);
    atomicAdd(&g_deg[c1], 1);
}

// 2) dinv = rsqrt(1+deg); reset deg for next replay; s = dinv*x; ab init = s
__global__ void k_nodeA(const float* __restrict__ x) {
    int i = blockIdx.x * blockDim.x + threadIdx.x;
    if (i >= NN) return;
    int cnt = g_deg[i];
    g_deg[i] = 0;                          // restore zero invariant for graph replay
    float d = rsqrtf((float)(1 + cnt));
    g_dinv[i] = d;
    float2 xv = ((const float2*)x)[i];
    float2 s = make_float2(xv.x * d, xv.y * d);
    g_s[i]  = s;
    g_ab[i] = s;
}

// 3) conv1 scatter in rank-2 basis (1 edge/thread): ab[col] += s[row]
//    (g_edge kept cache-resident: k_edge reuses it)
__global__ void k_scat1() {
    int e = blockIdx.x * blockDim.x + threadIdx.x;
    if (e >= NE) return;
    int2 rc = g_edge[e];
    float2 s = g_s[rc.x];
    red_add_v2(&g_ab[rc.y], s.x, s.y);
}

// 4) expand: h = dinv*(ab.x*W1row0 + ab.y*W1row1) + b1;
//    pr = We[0:16]^T h (fp16-packed), pc = We[17:33]^T h, z = (h@W2)*dinv; ox init = z
__global__ void k_nodeB(const float* __restrict__ W1, const float* __restrict__ b1,
                        const float* __restrict__ W2, const float* __restrict__ We) {
    int i = blockIdx.x * blockDim.x + threadIdx.x;
    if (i >= NN) return;
    float d = g_dinv[i];
    float2 ab = g_ab[i];
    float ax = ab.x * d, bx = ab.y * d;
    float z0 = 0.f, z1 = 0.f;
    float4 pr = make_float4(0.f, 0.f, 0.f, 0.f);
    float4 pc = make_float4(0.f, 0.f, 0.f, 0.f);
#pragma unroll
    for (int q = 0; q < 4; q++) {
        float4 w0 = ((const float4*)W1)[q];
        float4 w1 = ((const float4*)W1)[4 + q];
        float4 bq = ((const float4*)b1)[q];
        float4 h;
        h.x = fmaf(ax, w0.x, fmaf(bx, w1.x, bq.x));
        h.y = fmaf(ax, w0.y, fmaf(bx, w1.y, bq.y));
        h.z = fmaf(ax, w0.z, fmaf(bx, w1.z, bq.z));
        h.w = fmaf(ax, w0.w, fmaf(bx, w1.w, bq.w));
        float hv[4] = {h.x, h.y, h.z, h.w};
#pragma unroll
        for (int j = 0; j < 4; j++) {
            int k = q * 4 + j;
            float s = hv[j];
            float2 w2 = ((const float2*)W2)[k];
            z0 = fmaf(s, w2.x, z0);
            z1 = fmaf(s, w2.y, z1);
            float4 wr = ((const float4*)We)[k];
            float4 wc = ((const float4*)We)[17 + k];
            pr.x = fmaf(s, wr.x, pr.x); pr.y = fmaf(s, wr.y, pr.y);
            pr.z = fmaf(s, wr.z, pr.z); pr.w = fmaf(s, wr.w, pr.w);
            pc.x = fmaf(s, wc.x, pc.x); pc.y = fmaf(s, wc.y, pc.y);
            pc.z = fmaf(s, wc.z, pc.z); pc.w = fmaf(s, wc.w, pc.w);
        }
    }
    uint4 rrec;
    rrec.x = pack_h2(pr.x, pr.y);
    rrec.y = pack_h2(pr.z, pr.w);
    rrec.z = __float_as_uint(z0 * d);
    rrec.w = __float_as_uint(z1 * d);
    g_r16[i] = rrec;
    g_pc[i]  = pc;
    g_ox[i]  = make_float2(z0 * d, z1 * d);
}

// 5) edge pass (1 edge/thread): acc = pr[r]+pc[c]+ea*We16+be -> relu -> log_softmax(4)
//    r-side = ONE 16B gather; last use of g_edge -> evict-first; streaming output
__global__ void k_edge(const float* __restrict__ ea,
                       const float* __restrict__ We,
                       const float* __restrict__ be,
                       float* __restrict__ out_e) {
    int e = blockIdx.x * blockDim.x + threadIdx.x;
    if (e >= NE) return;
    float4 w16 = __ldg((const float4*)We + 16);
    float4 bev = __ldg((const float4*)be);

    int2 rc = __ldcs(&g_edge[e]);               // last use: evict-first
    int r = rc.x, c = rc.y;

    uint4  rr = g_r16[r];                       // single 16B r-side gather
    float2 p01 = unpack_h2(rr.x);
    float2 p23 = unpack_h2(rr.y);
    float  zx = __uint_as_float(rr.z);
    float  zy = __uint_as_float(rr.w);
    float4 pc = g_pc[c];
    float  eav = __ldcs(ea + e);

    float4 acc;
    acc.x = fmaf(eav, w16.x, bev.x) + p01.x + pc.x;
    acc.y = fmaf(eav, w16.y, bev.y) + p01.y + pc.y;
    acc.z = fmaf(eav, w16.z, bev.z) + p23.x + pc.z;
    acc.w = fmaf(eav, w16.w, bev.w) + p23.y + pc.w;

    acc.x = fmaxf(acc.x, 0.f); acc.y = fmaxf(acc.y, 0.f);
    acc.z = fmaxf(acc.z, 0.f); acc.w = fmaxf(acc.w, 0.f);
    float m = fmaxf(fmaxf(acc.x, acc.y), fmaxf(acc.z, acc.w));
    float s = __expf(acc.x - m) + __expf(acc.y - m) +
              __expf(acc.z - m) + __expf(acc.w - m);
    float l = m + __logf(s);
    __stcs((float4*)out_e + e,
           make_float4(acc.x - l, acc.y - l, acc.z - l, acc.w - l));

    red_add_v2(&g_ox[c], zx, zy);
}

// 6) node output: log_softmax(ox_acc*dinv + b2) over 2 classes
__global__ void k_nodeC(const float* __restrict__ b2, float* __restrict__ out_n) {
    int i = blockIdx.x * blockDim.x + threadIdx.x;
    if (i >= NN) return;
    float d = g_dinv[i];
    float2 bb = *((const float2*)b2);
    float2 v = g_ox[i];
    v.x = fmaf(v.x, d, bb.x);
    v.y = fmaf(v.y, d, bb.y);
    float m = fmaxf(v.x, v.y);
    float l = m + __logf(__expf(v.x - m) + __expf(v.y - m));
    ((float2*)out_n)[i] = make_float2(v.x - l, v.y - l);
}

extern "C" void kernel_launch(void* const* d_in, const int* in_sizes, int n_in,
                              void* d_out, int out_size) {
    const float *x = 0, *ea = 0, *W1 = 0, *b1 = 0, *We = 0, *be = 0, *W2 = 0, *b2 = 0;
    const int* ei32 = 0;
    for (int i = 0; i < n_in; i++) {
        switch (in_sizes[i]) {
            case 200000:   x    = (const float*)d_in[i]; break;
            case 6400000:  ei32 = (const int*)d_in[i];   break;
            case 12800000: ei32 = (const int*)d_in[i];   break;
            case 3200000:  ea   = (const float*)d_in[i]; break;
            case 132:      We   = (const float*)d_in[i]; break;
            case 16:       b1   = (const float*)d_in[i]; break;
            case 4:        be   = (const float*)d_in[i]; break;
            case 2:        b2   = (const float*)d_in[i]; break;
            case 32:
                if (!W1) W1 = (const float*)d_in[i];
                else     W2 = (const float*)d_in[i];
                break;
            default: break;
        }
    }

    float* out = (float*)d_out;
    float* out_n = out;             // [N,2]
    float* out_e = out + 2 * NN;    // [E,4]

    const int BT_N = 256;
    const int BT_E = 128;
    const int NB_N  = (NN + BT_N - 1) / BT_N;
    const int NB_E  = (NE + BT_E - 1) / BT_E;
    const int NB_E2 = (NE / 2 + 512 - 1) / 512;

    k_deg   <<<NB_E2, 512>>>(ei32);
    k_nodeA <<<NB_N, BT_N>>>(x);
    k_scat1 <<<NB_E, BT_E>>>();
    k_nodeB <<<NB_N, BT_N>>>(W1, b1, W2, We);
    k_edge  <<<NB_E, BT_E>>>(ea, We, be, out_e);
    k_nodeC <<<NB_N, BT_N>>>(b2, out_n);
}

// round 15
// speedup vs baseline: 1.0021x; 1.0009x over previous
#include <cuda_runtime.h>
#include <cuda_fp16.h>

#define NN 100000
#define NE 3200000

// ---- scratch (static __device__, zero-init at module load) ----
__device__ int    g_deg[NN];         // degree counters (reset by k_nodeA each run)
__device__ float  g_dinv[NN];        // rsqrt(1+deg)
__device__ float2 g_s[NN];           // s[i] = dinv[i] * x[i]  (rank-2 coords)
__device__ float2 g_ab[NN];          // conv1 accumulator in rank-2 basis (init = s[i])
// r-side packed record, ONE 16B gather per edge:
//   .x = half2(pr.x, pr.y)  .y = half2(pr.z, pr.w)   (edge-MLP r-projection, fp16)
//   .z = bits(z.x)          .w = bits(z.y)           (conv2 operand, fp32)
__device__ uint4  g_r16[NN];
__device__ float4 g_pc[NN];          // c-side proj: We[17:33]^T h  (fp32)
__device__ float2 g_ox[NN];          // conv2 accumulator (unscaled)
__device__ int2   g_edge[NE];        // (row, col) packed

// ---- fp16 pack/unpack helpers ----
__device__ __forceinline__ unsigned pack_h2(float a, float b) {
    unsigned lo = __half_as_ushort(__float2half_rn(a));
    unsigned hi = __half_as_ushort(__float2half_rn(b));
    return lo | (hi << 16);
}
__device__ __forceinline__ float2 unpack_h2(unsigned u) {
    float a = __half2float(__ushort_as_half((unsigned short)(u & 0xFFFFu)));
    float b = __half2float(__ushort_as_half((unsigned short)(u >> 16)));
    return make_float2(a, b);
}

// ---- vectorized L2 reduction (global address space) ----
__device__ __forceinline__ void red_add_v2(float2* addr, float a, float b) {
    unsigned long long ga;
    asm("cvta.to.global.u64 %0, %1;" : "=l"(ga) : "l"(addr));
    asm volatile("red.global.add.v2.f32 [%0], {%1, %2};"
                 :: "l"(ga), "f"(a), "f"(b) : "memory");
}

// 1) decode edge index (2 edges/thread, streaming loads) -> packed int2 + degree count.
//    int64-vs-int32 layout detected per warp: odd words of the first 16 int64s all
//    zero <=> int64 (random indices in [0,100000) are never all-zero there).
__global__ void k_deg(const int* __restrict__ ei32) {
    int lane = threadIdx.x & 31;
    int w = ei32[lane];
    unsigned mask = __ballot_sync(0xFFFFFFFFu, (lane & 1) ? (w == 0) : true);
    bool is64 = (mask == 0xFFFFFFFFu);

    int t = blockIdx.x * blockDim.x + threadIdx.x;
    if (t >= NE / 2) return;
    int r0, c0, r1, c1;
    if (is64) {
        int4 rr = __ldcs((const int4*)ei32 + t);              // longs 2t,2t+1 (rows)
        int4 cc = __ldcs((const int4*)ei32 + (NE / 2) + t);   // longs NE+2t.. (cols)
        r0 = rr.x; r1 = rr.z;
        c0 = cc.x; c1 = cc.z;
    } else {
        int2 rr = __ldcs((const int2*)ei32 + t);
        int2 cc = __ldcs((const int2*)(ei32 + NE) + t);
        r0 = rr.x; r1 = rr.y;
        c0 = cc.x; c1 = cc.y;
    }
    ((int4*)g_edge)[t] = make_int4(r0, c0, r1, c1);
    atomicAdd(&g_deg[c0], 1);
    atomicAdd(&g_deg[c1], 1);
}

// 2) dinv = rsqrt(1+deg); reset deg for next replay; s = dinv*x; ab init = s
__global__ void k_nodeA(const float* __restrict__ x) {
    int i = blockIdx.x * blockDim.x + threadIdx.x;
    if (i >= NN) return;
    int cnt = g_deg[i];
    g_deg[i] = 0;                          // restore zero invariant for graph replay
    float d = rsqrtf((float)(1 + cnt));
    g_dinv[i] = d;
    float2 xv = ((const float2*)x)[i];
    float2 s = make_float2(xv.x * d, xv.y * d);
    g_s[i]  = s;
    g_ab[i] = s;
}

// 3) conv1 scatter in rank-2 basis, 2 edges/thread (int4 edge load halves
//    edge-list sector-ops): ab[col] += s[row]
__global__ void k_scat1() {
    int t = blockIdx.x * blockDim.x + threadIdx.x;
    if (t >= NE / 2) return;
    int4 e2 = ((const int4*)g_edge)[t];    // (r0,c0,r1,c1) one 16B op
    float2 s0 = g_s[e2.x];
    float2 s1 = g_s[e2.z];
    red_add_v2(&g_ab[e2.y], s0.x, s0.y);
    red_add_v2(&g_ab[e2.w], s1.x, s1.y);
}

// 4) expand: h = dinv*(ab.x*W1row0 + ab.y*W1row1) + b1;
//    pr = We[0:16]^T h (fp16-packed), pc = We[17:33]^T h, z = (h@W2)*dinv; ox init = z
__global__ void k_nodeB(const float* __restrict__ W1, const float* __restrict__ b1,
                        const float* __restrict__ W2, const float* __restrict__ We) {
    int i = blockIdx.x * blockDim.x + threadIdx.x;
    if (i >= NN) return;
    float d = g_dinv[i];
    float2 ab = g_ab[i];
    float ax = ab.x * d, bx = ab.y * d;
    float z0 = 0.f, z1 = 0.f;
    float4 pr = make_float4(0.f, 0.f, 0.f, 0.f);
    float4 pc = make_float4(0.f, 0.f, 0.f, 0.f);
#pragma unroll
    for (int q = 0; q < 4; q++) {
        float4 w0 = ((const float4*)W1)[q];
        float4 w1 = ((const float4*)W1)[4 + q];
        float4 bq = ((const float4*)b1)[q];
        float4 h;
        h.x = fmaf(ax, w0.x, fmaf(bx, w1.x, bq.x));
        h.y = fmaf(ax, w0.y, fmaf(bx, w1.y, bq.y));
        h.z = fmaf(ax, w0.z, fmaf(bx, w1.z, bq.z));
        h.w = fmaf(ax, w0.w, fmaf(bx, w1.w, bq.w));
        float hv[4] = {h.x, h.y, h.z, h.w};
#pragma unroll
        for (int j = 0; j < 4; j++) {
            int k = q * 4 + j;
            float s = hv[j];
            float2 w2 = ((const float2*)W2)[k];
            z0 = fmaf(s, w2.x, z0);
            z1 = fmaf(s, w2.y, z1);
            float4 wr = ((const float4*)We)[k];
            float4 wc = ((const float4*)We)[17 + k];
            pr.x = fmaf(s, wr.x, pr.x); pr.y = fmaf(s, wr.y, pr.y);
            pr.z = fmaf(s, wr.z, pr.z); pr.w = fmaf(s, wr.w, pr.w);
            pc.x = fmaf(s, wc.x, pc.x); pc.y = fmaf(s, wc.y, pc.y);
            pc.z = fmaf(s, wc.z, pc.z); pc.w = fmaf(s, wc.w, pc.w);
        }
    }
    uint4 rrec;
    rrec.x = pack_h2(pr.x, pr.y);
    rrec.y = pack_h2(pr.z, pr.w);
    rrec.z = __float_as_uint(z0 * d);
    rrec.w = __float_as_uint(z1 * d);
    g_r16[i] = rrec;
    g_pc[i]  = pc;
    g_ox[i]  = make_float2(z0 * d, z1 * d);
}

// 5) edge pass (1 edge/thread): acc = pr[r]+pc[c]+ea*We16+be -> relu -> log_softmax(4)
//    r-side = ONE 16B gather; last use of g_edge -> evict-first; streaming output
__global__ void k_edge(const float* __restrict__ ea,
                       const float* __restrict__ We,
                       const float* __restrict__ be,
                       float* __restrict__ out_e) {
    int e = blockIdx.x * blockDim.x + threadIdx.x;
    if (e >= NE) return;
    float4 w16 = __ldg((const float4*)We + 16);
    float4 bev = __ldg((const float4*)be);

    int2 rc = __ldcs(&g_edge[e]);               // last use: evict-first
    int r = rc.x, c = rc.y;

    uint4  rr = g_r16[r];                       // single 16B r-side gather
    float2 p01 = unpack_h2(rr.x);
    float2 p23 = unpack_h2(rr.y);
    float  zx = __uint_as_float(rr.z);
    float  zy = __uint_as_float(rr.w);
    float4 pc = g_pc[c];
    float  eav = __ldcs(ea + e);

    float4 acc;
    acc.x = fmaf(eav, w16.x, bev.x) + p01.x + pc.x;
    acc.y = fmaf(eav, w16.y, bev.y) + p01.y + pc.y;
    acc.z = fmaf(eav, w16.z, bev.z) + p23.x + pc.z;
    acc.w = fmaf(eav, w16.w, bev.w) + p23.y + pc.w;

    acc.x = fmaxf(acc.x, 0.f); acc.y = fmaxf(acc.y, 0.f);
    acc.z = fmaxf(acc.z, 0.f); acc.w = fmaxf(acc.w, 0.f);
    float m = fmaxf(fmaxf(acc.x, acc.y), fmaxf(acc.z, acc.w));
    float s = __expf(acc.x - m) + __expf(acc.y - m) +
              __expf(acc.z - m) + __expf(acc.w - m);
    float l = m + __logf(s);
    __stcs((float4*)out_e + e,
           make_float4(acc.x - l, acc.y - l, acc.z - l, acc.w - l));

    red_add_v2(&g_ox[c], zx, zy);
}

// 6) node output: log_softmax(ox_acc*dinv + b2) over 2 classes
__global__ void k_nodeC(const float* __restrict__ b2, float* __restrict__ out_n) {
    int i = blockIdx.x * blockDim.x + threadIdx.x;
    if (i >= NN) return;
    float d = g_dinv[i];
    float2 bb = *((const float2*)b2);
    float2 v = g_ox[i];
    v.x = fmaf(v.x, d, bb.x);
    v.y = fmaf(v.y, d, bb.y);
    float m = fmaxf(v.x, v.y);
    float l = m + __logf(__expf(v.x - m) + __expf(v.y - m));
    ((float2*)out_n)[i] = make_float2(v.x - l, v.y - l);
}

extern "C" void kernel_launch(void* const* d_in, const int* in_sizes, int n_in,
                              void* d_out, int out_size) {
    const float *x = 0, *ea = 0, *W1 = 0, *b1 = 0, *We = 0, *be = 0, *W2 = 0, *b2 = 0;
    const int* ei32 = 0;
    for (int i = 0; i < n_in; i++) {
        switch (in_sizes[i]) {
            case 200000:   x    = (const float*)d_in[i]; break;
            case 6400000:  ei32 = (const int*)d_in[i];   break;
            case 12800000: ei32 = (const int*)d_in[i];   break;
            case 3200000:  ea   = (const float*)d_in[i]; break;
            case 132:      We   = (const float*)d_in[i]; break;
            case 16:       b1   = (const float*)d_in[i]; break;
            case 4:        be   = (const float*)d_in[i]; break;
            case 2:        b2   = (const float*)d_in[i]; break;
            case 32:
                if (!W1) W1 = (const float*)d_in[i];
                else     W2 = (const float*)d_in[i];
                break;
            default: break;
        }
    }

    float* out = (float*)d_out;
    float* out_n = out;             // [N,2]
    float* out_e = out + 2 * NN;    // [E,4]

    const int BT_N = 256;
    const int BT_E = 128;
    const int NB_N  = (NN + BT_N - 1) / BT_N;
    const int NB_E  = (NE + BT_E - 1) / BT_E;
    const int NB_E2 = (NE / 2 + 512 - 1) / 512;
    const int NB_S2 = (NE / 2 + BT_E - 1) / BT_E;

    k_deg   <<<NB_E2, 512>>>(ei32);
    k_nodeA <<<NB_N, BT_N>>>(x);
    k_scat1 <<<NB_S2, BT_E>>>();
    k_nodeB <<<NB_N, BT_N>>>(W1, b1, W2, We);
    k_edge  <<<NB_E, BT_E>>>(ea, We, be, out_e);
    k_nodeC <<<NB_N, BT_N>>>(b2, out_n);
}